// round 17
// baseline (speedup 1.0000x reference)
#include <cuda_runtime.h>
#include <cuda_fp16.h>
#include <cstdint>

#define NN 100000
#define NE 800000
#define FH 64
#define FO 16
#define SCAN_T 1024
#define G1_TILES 2          // 64-row tiles per gemm64 block

// ---------------- scratch ----------------------------------------------------
__device__ int     g_cnt[NN + 128];   // [0,NN): in-degree; [NN,..): lookback slots
__device__ int     g_off[NN];         // CSR offsets; AFTER scatter = end pointers
__device__ float   g_dinv[NN];
__device__ int2    g_rc[NE];          // converted (src,dst) per edge
__device__ int2    g_sn[NE];          // CSR payload: (src, nrm bits)
__device__ __half2 g_tmp1h[(size_t)NN * 32];   // x @ W1, fp16
__device__ __half2 g_tmp2h[(size_t)NN * 8];    // gcn1(h) @ W2, fp16
__device__ __half  g_w1t[64 * 64];    // W1^T fp16: [n][k]
__device__ __half  g_w2t[16 * 64];    // W2^T fp16: [n][k]

// ---------------- helpers ----------------------------------------------------
__device__ __forceinline__ uint32_t smem_u32(const void* p) {
    return (uint32_t)__cvta_generic_to_shared(p);
}
__device__ __forceinline__ void cp_async16(uint32_t dst, const void* src, int sz) {
    asm volatile("cp.async.ca.shared.global [%0], [%1], 16, %2;"
                 :: "r"(dst), "l"(src), "r"(sz));
}
__device__ __forceinline__ int block_detect64(const void* edge, int n_nodes) {
    const long long* p = (const long long*)edge;
    long long v = p[threadIdx.x & 255];
    bool bad = (v < 0 || v >= (long long)n_nodes);
    return __syncthreads_or(bad ? 1 : 0) ? 0 : 1;
}
__device__ __forceinline__ void acc8(float* a, uint4 r, float w) {
    float2 p;
    p = __half22float2(*(__half2*)&r.x); a[0] += p.x * w; a[1] += p.y * w;
    p = __half22float2(*(__half2*)&r.y); a[2] += p.x * w; a[3] += p.y * w;
    p = __half22float2(*(__half2*)&r.z); a[4] += p.x * w; a[5] += p.y * w;
    p = __half22float2(*(__half2*)&r.w); a[6] += p.x * w; a[7] += p.y * w;
}

// ---------------- hist + edge convert + (last block) weight prep -------------
__global__ void k_hist(const void* edge, int E, int n_nodes,
                       const float* __restrict__ W1,
                       const float* __restrict__ W2) {
    if (blockIdx.x == gridDim.x - 1) {        // weight-prep block (concurrent)
        int tid = threadIdx.x;
        for (int i = tid; i < 64 * 64; i += 256) {
            int k = i >> 6, nn = i & 63;      // W1[k][n] -> w1t[n][k]
            g_w1t[nn * 64 + k] = __float2half_rn(W1[i]);
        }
        for (int i = tid; i < 64 * 16; i += 256) {
            int k = i >> 4, nn = i & 15;      // W2[k][n] -> w2t[n][k]
            g_w2t[nn * 64 + k] = __float2half_rn(W2[i]);
        }
        return;
    }
    int is64 = block_detect64(edge, n_nodes);
    int e = blockIdx.x * blockDim.x + threadIdx.x;
    if (e >= E) return;
    int r, c;
    if (is64) {
        const long long* p = (const long long*)edge;
        r = (int)p[e]; c = (int)p[e + E];
    } else {
        const int* p = (const int*)edge;
        r = p[e]; c = p[e + E];
    }
    g_rc[e] = make_int2(r, c);
    atomicAdd(&g_cnt[c], 1);
}

// ---------------- fused scan (deadlock-free lookback) + dinv -----------------
__global__ void k_scan(int n) {
    __shared__ int s[SCAN_T];
    __shared__ int s_pref;
    int b = blockIdx.x, t = threadIdx.x;
    int i = b * SCAN_T + t;
    int val = 0;
    if (i < n) {
        val = g_cnt[i];
        g_dinv[i] = rsqrtf((float)val + 1.0f);   // +1 self loop
    }
    s[t] = val;
    __syncthreads();
    for (int d = 1; d < SCAN_T; d <<= 1) {
        int add = (t >= d) ? s[t - d] : 0;
        __syncthreads();
        s[t] += add;
        __syncthreads();
    }
    if (t == SCAN_T - 1) atomicExch(&g_cnt[NN + b], s[t] + 1);   // publish first
    if (t == 0) s_pref = 0;
    __syncthreads();
    if (t < b) {
        int v;
        do { v = atomicAdd(&g_cnt[NN + t], 0); } while (v == 0);
        atomicAdd(&s_pref, v - 1);
    }
    __syncthreads();
    if (i < n) g_off[i] = s[t] - val + s_pref;
}

// ---------------- merged: gemm64 (blocks [0,g1b)) + scatter (rest) -----------
__global__ void k_scat_gemm(int E,
                            const float* __restrict__ A,
                            __half2* __restrict__ outh, int n, int g1b) {
    __shared__ float  Xf[2][64][72];   // gemm: fp32 X tiles (reused for C staging)
    __shared__ __half Wts[64][72];     // gemm: W1^T [n][k]

    int tid = threadIdx.x;

    if (blockIdx.x >= g1b) {
        // ---------------- scatter branch ----------------
        int sb = blockIdx.x - g1b;
        if (sb == 0 && tid < 128)
            g_cnt[NN + tid] = 0;              // reset lookback slots for next call
        int e = sb * blockDim.x + tid;
        if (e >= E) return;
        int2 rc = g_rc[e];
        float nr = g_dinv[rc.x] * g_dinv[rc.y];
        int pos = atomicAdd(&g_off[rc.y], 1);
        g_sn[pos] = make_int2(rc.x, __float_as_int(nr));
        return;
    }

    // ---------------- gemm64 branch ----------------
    int lane = tid & 31;
    int warp = tid >> 5;
    int q  = warp >> 2;                // col-half
    int w2 = warp & 3;                 // row group
    int g = lane >> 2, t = lane & 3;
    int row0 = w2 * 16;

    for (int idx = tid; idx < 512; idx += 256) {
        uint4 v = *(const uint4*)&g_w1t[idx * 8];
        *(uint4*)&Wts[idx >> 3][(idx & 7) * 8] = v;
    }

    int tile0 = blockIdx.x * G1_TILES;
    {
        int rb = tile0 * 64;
#pragma unroll
        for (int j = 0; j < 4; j++) {
            int idx = tid + j * 256;
            int r = idx >> 4, k4 = (idx & 15) << 2;
            int gr = rb + r;
            cp_async16(smem_u32(&Xf[0][r][k4]), A + (size_t)gr * 64 + k4,
                       (gr < n) ? 16 : 0);
        }
        asm volatile("cp.async.commit_group;");
    }

    for (int tt = 0; tt < G1_TILES; tt++) {
        int buf = tt & 1;
        int rb  = (tile0 + tt) * 64;

        if (tt + 1 < G1_TILES) {
            int rb2 = rb + 64;
#pragma unroll
            for (int j = 0; j < 4; j++) {
                int idx = tid + j * 256;
                int r = idx >> 4, k4 = (idx & 15) << 2;
                int gr = rb2 + r;
                cp_async16(smem_u32(&Xf[buf ^ 1][r][k4]), A + (size_t)gr * 64 + k4,
                           (gr < n) ? 16 : 0);
            }
            asm volatile("cp.async.commit_group;");
            asm volatile("cp.async.wait_group 1;");
        } else {
            asm volatile("cp.async.wait_group 0;");
        }
        __syncthreads();

        float acc[4][4];
#pragma unroll
        for (int j = 0; j < 4; j++)
#pragma unroll
            for (int m = 0; m < 4; m++) acc[j][m] = 0.f;

#pragma unroll
        for (int k0 = 0; k0 < 64; k0 += 16) {
            float2 f0 = *(const float2*)&Xf[buf][row0 + g    ][k0 + 2 * t];
            float2 f1 = *(const float2*)&Xf[buf][row0 + g + 8][k0 + 2 * t];
            float2 f2 = *(const float2*)&Xf[buf][row0 + g    ][k0 + 2 * t + 8];
            float2 f3 = *(const float2*)&Xf[buf][row0 + g + 8][k0 + 2 * t + 8];
            __half2 h0 = __floats2half2_rn(f0.x, f0.y);
            __half2 h1 = __floats2half2_rn(f1.x, f1.y);
            __half2 h2 = __floats2half2_rn(f2.x, f2.y);
            __half2 h3 = __floats2half2_rn(f3.x, f3.y);
            unsigned ra0 = *(unsigned*)&h0, ra1 = *(unsigned*)&h1;
            unsigned ra2 = *(unsigned*)&h2, ra3 = *(unsigned*)&h3;
#pragma unroll
            for (int j = 0; j < 4; j++) {
                int nt = q * 4 + j;
                unsigned rb0 = *(const unsigned*)&Wts[nt * 8 + g][k0 + 2 * t];
                unsigned rb1 = *(const unsigned*)&Wts[nt * 8 + g][k0 + 2 * t + 8];
                asm volatile(
                    "mma.sync.aligned.m16n8k16.row.col.f32.f16.f16.f32 "
                    "{%0,%1,%2,%3}, {%4,%5,%6,%7}, {%8,%9}, {%0,%1,%2,%3};"
                    : "+f"(acc[j][0]), "+f"(acc[j][1]),
                      "+f"(acc[j][2]), "+f"(acc[j][3])
                    : "r"(ra0), "r"(ra1), "r"(ra2), "r"(ra3),
                      "r"(rb0), "r"(rb1));
            }
        }
        __syncthreads();

#pragma unroll
        for (int j = 0; j < 4; j++) {
            int nt = q * 4 + j;
            __half2 c0 = __floats2half2_rn(acc[j][0], acc[j][1]);
            __half2 c1 = __floats2half2_rn(acc[j][2], acc[j][3]);
            *(__half2*)&Xf[buf][row0 + g    ][nt * 4 + t] = c0;
            *(__half2*)&Xf[buf][row0 + g + 8][nt * 4 + t] = c1;
        }
        __syncthreads();

        for (int idx = tid; idx < 512; idx += 256) {
            int r = idx >> 3, c = idx & 7;
            int gr = rb + r;
            if (gr < n) {
                uint4 v = *(const uint4*)&Xf[buf][r][c * 4];
                *(uint4*)&outh[(size_t)gr * 32 + c * 4] = v;
            }
        }
        __syncthreads();
    }
}

// ---------------- fused layer-2a: agg1 (into smem, unroll 4) + gemm16 --------
__global__ void k_layer2a(const __half2* __restrict__ tmp,
                          const float4* __restrict__ b1,
                          __half2* __restrict__ outh, int n) {
    __shared__ __half Hs[128][72];
    __shared__ __half Wts[16][72];

    int tid  = threadIdx.x;
    int base = blockIdx.x * 128;
    int lane = tid & 31;
    int warp = tid >> 5;
    int g = lane >> 2, t = lane & 3;
    int l = tid & 7;                     // lane-in-node: half2 cols [4l, 4l+4)

    if (tid < 128) {
        uint4 v = *(const uint4*)&g_w2t[tid * 8];
        *(uint4*)&Wts[tid >> 3][(tid & 7) * 8] = v;
    }

    // Phase 1: aggregate 128 nodes, 32 nodes per batch (8 threads per node)
#pragma unroll
    for (int batch = 0; batch < 4; batch++) {
        int node = base + batch * 32 + (tid >> 3);
        float a[8] = {0.f, 0.f, 0.f, 0.f, 0.f, 0.f, 0.f, 0.f};
        if (node < n) {
            float di = g_dinv[node];
            float ws = di * di;
            uint4 raw = *(const uint4*)&tmp[(size_t)node * 32 + 4 * l];
            acc8(a, raw, ws);

            int e1 = g_off[node];
            int e  = e1 - g_cnt[node];
            for (; e + 4 <= e1; e += 4) {
                int2 q0 = g_sn[e];
                int2 q1 = g_sn[e + 1];
                int2 q2 = g_sn[e + 2];
                int2 q3 = g_sn[e + 3];
                uint4 r0 = *(const uint4*)&tmp[(size_t)q0.x * 32 + 4 * l];
                uint4 r1 = *(const uint4*)&tmp[(size_t)q1.x * 32 + 4 * l];
                uint4 r2 = *(const uint4*)&tmp[(size_t)q2.x * 32 + 4 * l];
                uint4 r3 = *(const uint4*)&tmp[(size_t)q3.x * 32 + 4 * l];
                acc8(a, r0, __int_as_float(q0.y));
                acc8(a, r1, __int_as_float(q1.y));
                acc8(a, r2, __int_as_float(q2.y));
                acc8(a, r3, __int_as_float(q3.y));
            }
            for (; e < e1; e++) {
                int2 q0 = g_sn[e];
                uint4 r0 = *(const uint4*)&tmp[(size_t)q0.x * 32 + 4 * l];
                acc8(a, r0, __int_as_float(q0.y));
            }
            float4 bb0 = b1[2 * l];
            float4 bb1 = b1[2 * l + 1];
            a[0] = fmaxf(a[0] + bb0.x, 0.f); a[1] = fmaxf(a[1] + bb0.y, 0.f);
            a[2] = fmaxf(a[2] + bb0.z, 0.f); a[3] = fmaxf(a[3] + bb0.w, 0.f);
            a[4] = fmaxf(a[4] + bb1.x, 0.f); a[5] = fmaxf(a[5] + bb1.y, 0.f);
            a[6] = fmaxf(a[6] + bb1.z, 0.f); a[7] = fmaxf(a[7] + bb1.w, 0.f);
        }
        __half2 o0 = __floats2half2_rn(a[0], a[1]);
        __half2 o1 = __floats2half2_rn(a[2], a[3]);
        __half2 o2 = __floats2half2_rn(a[4], a[5]);
        __half2 o3 = __floats2half2_rn(a[6], a[7]);
        uint4 ov;
        ov.x = *(unsigned*)&o0; ov.y = *(unsigned*)&o1;
        ov.z = *(unsigned*)&o2; ov.w = *(unsigned*)&o3;
        *(uint4*)&Hs[batch * 32 + (tid >> 3)][l * 8] = ov;
    }
    __syncthreads();

    // Phase 2: MMA 128x16 = Hs @ W2t; emit fp16
    int row0 = warp * 16;
    float acc[2][4];
#pragma unroll
    for (int nt = 0; nt < 2; nt++)
#pragma unroll
        for (int j = 0; j < 4; j++) acc[nt][j] = 0.f;

#pragma unroll
    for (int k0 = 0; k0 < 64; k0 += 16) {
        unsigned ra0 = *(const unsigned*)&Hs[row0 + g    ][k0 + 2 * t];
        unsigned ra1 = *(const unsigned*)&Hs[row0 + g + 8][k0 + 2 * t];
        unsigned ra2 = *(const unsigned*)&Hs[row0 + g    ][k0 + 2 * t + 8];
        unsigned ra3 = *(const unsigned*)&Hs[row0 + g + 8][k0 + 2 * t + 8];
#pragma unroll
        for (int nt = 0; nt < 2; nt++) {
            unsigned rb0 = *(const unsigned*)&Wts[nt * 8 + g][k0 + 2 * t];
            unsigned rb1 = *(const unsigned*)&Wts[nt * 8 + g][k0 + 2 * t + 8];
            asm volatile(
                "mma.sync.aligned.m16n8k16.row.col.f32.f16.f16.f32 "
                "{%0,%1,%2,%3}, {%4,%5,%6,%7}, {%8,%9}, {%0,%1,%2,%3};"
                : "+f"(acc[nt][0]), "+f"(acc[nt][1]),
                  "+f"(acc[nt][2]), "+f"(acc[nt][3])
                : "r"(ra0), "r"(ra1), "r"(ra2), "r"(ra3),
                  "r"(rb0), "r"(rb1));
        }
    }

#pragma unroll
    for (int nt = 0; nt < 2; nt++) {
        int c0 = nt * 8 + 2 * t;             // even column
        int gr0 = base + row0 + g;
        int gr1 = gr0 + 8;
        if (gr0 < n)
            outh[(size_t)gr0 * 8 + (c0 >> 1)] = __floats2half2_rn(acc[nt][0], acc[nt][1]);
        if (gr1 < n)
            outh[(size_t)gr1 * 8 + (c0 >> 1)] = __floats2half2_rn(acc[nt][2], acc[nt][3]);
    }
}

// ---------------- aggregation, layer 2 (F=16, fp16 src, unroll 8) ------------
__global__ void k_agg2h(const __half2* __restrict__ tmp,
                        const float2* __restrict__ b2,
                        float2* __restrict__ out, int n) {
    int i = (blockIdx.x * blockDim.x + threadIdx.x) >> 3;
    int l = threadIdx.x & 7;
    if (i >= n) return;
    float di = g_dinv[i];
    float ws = di * di;
    float2 v = __half22float2(tmp[(size_t)i * 8 + l]);
    float a0 = v.x * ws, a1 = v.y * ws;

    int e1 = g_off[i];
    int cnt = g_cnt[i];
    int e  = e1 - cnt;
    for (; e + 8 <= e1; e += 8) {
        int2 q[8];
        float2 tv[8];
#pragma unroll
        for (int j = 0; j < 8; j++) q[j] = g_sn[e + j];
#pragma unroll
        for (int j = 0; j < 8; j++)
            tv[j] = __half22float2(tmp[(size_t)q[j].x * 8 + l]);
#pragma unroll
        for (int j = 0; j < 8; j++) {
            float w = __int_as_float(q[j].y);
            a0 += tv[j].x * w; a1 += tv[j].y * w;
        }
    }
    for (; e < e1; e++) {
        int2 q = g_sn[e];
        float2 tv = __half22float2(tmp[(size_t)q.x * 8 + l]);
        float w = __int_as_float(q.y);
        a0 += tv.x * w; a1 += tv.y * w;
    }
    float2 bb = b2[l];
    out[(size_t)i * 8 + l] = make_float2(a0 + bb.x, a1 + bb.y);
    if (l == 0) g_cnt[i] = 0;            // restore pre-call invariant
}

// ---------------- launcher ---------------------------------------------------
extern "C" void kernel_launch(void* const* d_in, const int* in_sizes, int n_in,
                              void* d_out, int out_size) {
    const float* x  = (const float*)d_in[0];
    const void*  ei = d_in[1];
    const float* W1 = (const float*)d_in[2];
    const float* b1 = (const float*)d_in[3];
    const float* W2 = (const float*)d_in[4];
    const float* b2 = (const float*)d_in[5];
    float* out = (float*)d_out;

    const int n = in_sizes[0] / FH;
    const int E = in_sizes[1] / 2;

    __half2* tmp1h; cudaGetSymbolAddress((void**)&tmp1h, g_tmp1h);
    __half2* tmp2h; cudaGetSymbolAddress((void**)&tmp2h, g_tmp2h);

    const int T  = 256;
    const int gE = (E + T - 1) / T;
    const int nb = (n + SCAN_T - 1) / SCAN_T;
    const int tiles = (n + 63) / 64;
    const int g1b = (tiles + G1_TILES - 1) / G1_TILES;

    k_hist     <<<gE + 1, T>>>(ei, E, n, W1, W2);   // +1 block = weight prep
    k_scan     <<<nb, SCAN_T>>>(n);
    k_scat_gemm<<<g1b + gE, T>>>(E, x, tmp1h, n, g1b);   // scatter ∥ gemm64
    k_layer2a  <<<(n + 127) / 128, 256>>>(tmp1h, (const float4*)b1, tmp2h, n);
    k_agg2h    <<<(n * 8 + T - 1) / T, T>>>(tmp2h, (const float2*)b2,
                                            (float2*)out, n);

    (void)n_in; (void)out_size;
}